// round 1
// baseline (speedup 1.0000x reference)
#include <cuda_runtime.h>
#include <cuda_bf16.h>

// BandedJointEncoder: invert per-(b,z) upper-bidiagonal precision matrices.
//
// Input : mapped [B, T, 3*Z] float32, T=512, Z=32, C=96.
//   d[t] = mapped[b,t,32+2z] + 1      (diagonal of U)
//   s[t] = mapped[b,t,33+2z]          (superdiagonal of U, t < T-1)
// Outputs (concatenated in d_out, reference return order):
//   mapped_mean     [B, Z, T]      : mean[b,z,t] = mapped[b,t,z]
//   cov_tril_lower  [B, Z, T, T]   : L[r,c] = (1/d_r) * prod_{k=c}^{r-1} (-s_k/d_k), r>=c; else 0
//
// One CTA per (b,z). Thread c owns column c: forward recurrence down rows,
// every iteration stores one fully-coalesced 2KB row (zeros included).

#define T_DIM 512
#define Z_DIM 32
#define C_DIM 96

__global__ __launch_bounds__(T_DIM)
void banded_joint_encoder_kernel(const float* __restrict__ in,
                                 float* __restrict__ out_mean,
                                 float* __restrict__ out_cov)
{
    const int bz = blockIdx.x;           // b*Z + z
    const int b  = bz >> 5;
    const int z  = bz & 31;
    const int c  = threadIdx.x;          // column index 0..511

    __shared__ float sh_t[T_DIM];        // t[k] = -s[k]/d[k]
    __shared__ float sh_invd[T_DIM];     // 1/d[k]

    const float* base = in + (size_t)b * T_DIM * C_DIM;

    // ---- prologue: load d/s for row index 'c', emit mean, fill shared ----
    {
        const float* row_in = base + (size_t)c * C_DIM;
        float dv  = row_in[32 + 2 * z] + 1.0f;
        float sv  = row_in[33 + 2 * z];          // element T-1 read but never used
        float inv = 1.0f / dv;
        sh_invd[c] = inv;
        sh_t[c]    = -sv * inv;

        out_mean[(size_t)bz * T_DIM + c] = row_in[z];
    }
    __syncthreads();

    // ---- mainloop: one output row per iteration, coalesced 2KB store ----
    float p = 1.0f;
    float* col_ptr = out_cov + (size_t)bz * T_DIM * T_DIM + c;

    #pragma unroll 4
    for (int r = 0; r < T_DIM; ++r) {
        const float iv = sh_invd[r];     // broadcast LDS, conflict-free
        const float tv = sh_t[r];
        const bool active = (r >= c);
        const float val = active ? p * iv : 0.0f;
        col_ptr[(size_t)r * T_DIM] = val;
        p = active ? p * tv : p;
    }
}

extern "C" void kernel_launch(void* const* d_in, const int* in_sizes, int n_in,
                              void* d_out, int out_size)
{
    const float* in = (const float*)d_in[0];
    float* out = (float*)d_out;

    const int B = in_sizes[0] / (T_DIM * C_DIM);   // 4 for the bench shapes

    float* out_mean = out;                                   // [B, Z, T]
    float* out_cov  = out + (size_t)B * Z_DIM * T_DIM;       // [B, Z, T, T]

    banded_joint_encoder_kernel<<<B * Z_DIM, T_DIM>>>(in, out_mean, out_cov);
}

// round 2
// speedup vs baseline: 1.0638x; 1.0638x over previous
#include <cuda_runtime.h>
#include <cuda_bf16.h>

// BandedJointEncoder: closed-form inverse of per-(b,z) upper-bidiagonal U.
//   d[t] = mapped[b,t,32+2z] + 1 ; s[t] = mapped[b,t,33+2z]
//   L[r,c] = inv_d[r] * prod_{k=c}^{r-1} (-s_k/d_k)  for r >= c, else 0
// Outputs: mean [B,Z,T] then cov_tril_lower [B,Z,T,T].
//
// R1: store-issue bound fix. Thread owns 4 consecutive columns -> STG.128.
// 512 threads = 4 row-groups x 128 column-quads. Row-group g>0 seeds its
// running products with a prefix product computed from shared 8-term blocks.

#define T_DIM 512
#define Z_DIM 32
#define C_DIM 96

__global__ __launch_bounds__(T_DIM)
void banded_joint_encoder_kernel(const float* __restrict__ in,
                                 float* __restrict__ out_mean,
                                 float* __restrict__ out_cov)
{
    const int bz  = blockIdx.x;          // b*Z + z
    const int b   = bz >> 5;
    const int z   = bz & 31;
    const int tid = threadIdx.x;

    __shared__ float2 sh_ti[T_DIM];      // {t[k], inv_d[k]}
    __shared__ float  sh_b8[T_DIM / 8];  // 8-term block products of t

    // ---- prologue: per-row t / inv_d, mean output ----
    {
        const float* row_in = in + ((size_t)b * T_DIM + tid) * C_DIM;
        float dv  = row_in[32 + 2 * z] + 1.0f;
        float sv  = row_in[33 + 2 * z];
        float inv = 1.0f / dv;
        sh_ti[tid] = make_float2(-sv * inv, inv);
        out_mean[(size_t)bz * T_DIM + tid] = row_in[z];
    }
    __syncthreads();

    if (tid < T_DIM / 8) {
        int k0 = tid * 8;
        float bprod = sh_ti[k0].x;
        #pragma unroll
        for (int j = 1; j < 8; ++j) bprod *= sh_ti[k0 + j].x;
        sh_b8[tid] = bprod;
    }
    __syncthreads();

    const int g  = tid >> 7;             // row group 0..3
    const int l  = tid & 127;            // column quad 0..127
    const int c0 = l << 2;               // first of 4 owned columns
    const int R0 = g << 7;               // first row of this group

    // ---- seed running products p_j = prod_{k=c_j}^{R0-1} t_k ----
    float p0 = 1.f, p1 = 1.f, p2 = 1.f, p3 = 1.f;
    if (c0 < R0) {
        // p3 over [c0+3, R0): head to 8-alignment, then 8-blocks
        int k = c0 + 3;
        int e = (k + 7) & ~7;            // <= R0 since c0+3 < R0 and R0 % 8 == 0... e=min needed
        if (e > R0) e = R0;
        float p = 1.f;
        for (; k < e; ++k) p *= sh_ti[k].x;
        for (; k + 8 <= R0; k += 8) p *= sh_b8[k >> 3];
        p3 = p;
        p2 = sh_ti[c0 + 2].x * p3;
        p1 = sh_ti[c0 + 1].x * p2;
        p0 = sh_ti[c0 + 0].x * p1;
    }

    // ---- main loop: 128 rows, one STG.128 per row per thread ----
    float4* out4 = (float4*)(out_cov + (size_t)bz * T_DIM * T_DIM) + l;

    #pragma unroll 4
    for (int r = R0; r < R0 + 128; ++r) {
        const float2 ti = sh_ti[r];      // broadcast LDS.64
        const float tv = ti.x, iv = ti.y;

        float4 v;
        bool a0 = (r >= c0);
        bool a1 = (r >= c0 + 1);
        bool a2 = (r >= c0 + 2);
        bool a3 = (r >= c0 + 3);
        v.x = a0 ? p0 * iv : 0.f;
        v.y = a1 ? p1 * iv : 0.f;
        v.z = a2 ? p2 * iv : 0.f;
        v.w = a3 ? p3 * iv : 0.f;
        if (a0) p0 *= tv;
        if (a1) p1 *= tv;
        if (a2) p2 *= tv;
        if (a3) p3 *= tv;

        out4[(size_t)r * (T_DIM / 4)] = v;
    }
}

extern "C" void kernel_launch(void* const* d_in, const int* in_sizes, int n_in,
                              void* d_out, int out_size)
{
    const float* in = (const float*)d_in[0];
    float* out = (float*)d_out;

    const int B = in_sizes[0] / (T_DIM * C_DIM);

    float* out_mean = out;                                // [B, Z, T]
    float* out_cov  = out + (size_t)B * Z_DIM * T_DIM;    // [B, Z, T, T]

    banded_joint_encoder_kernel<<<B * Z_DIM, T_DIM>>>(in, out_mean, out_cov);
}